// round 16
// baseline (speedup 1.0000x reference)
#include <cuda_runtime.h>
#include <math.h>

// ---------------- problem constants ----------------
#define B_   8
#define T_   1024
#define C_   768
#define H_   12
#define HS_  64
#define E_   8
#define F_   3072
#define N_   (B_*T_)     // 8192 tokens
#define BH_  (B_*H_)     // 96
#define C3_  (3*C_)      // 2304

#define ST_  36          // smem row stride (floats) for 32-deep GEMM tiles

// dynamic smem sizes
#define TG_SMEM  (3*128*ST_*2*4)             // 110592 (3-stage, A+B)
#define SC_SMEM  (128*68*2*4)                // 69632
#define PV_SMEM  ((6*128*20 + 6*16*72)*4)    // 89088

// transposed-weight slab offsets (floats)
#define WT_PROJ  0
#define WT_DW1   (WT_PROJ + C_*C_)
#define WT_DW2   (WT_DW1 + 2*C_*F_)
#define WT_DW3   (WT_DW2 + 2*F_*F_)
#define WT_SW1   (WT_DW3 + 2*F_*C_)
#define WT_SW2   (WT_SW1 + 6*C_*F_)
#define WT_TOTAL (WT_SW2 + 6*F_*C_)

// ---------------- scratch (device globals; no allocation) ----------------
__device__ float g_h1  [N_*C_];               // h1 (rounded), later h2r (rounded)
__device__ float g_qkv [N_*C3_];
__device__ float g_S   [(size_t)BH_*T_*T_];
__device__ float g_o   [N_*C_];
__device__ float g_h2  [N_*C_];               // exact h2
__device__ float g_mid1[(size_t)E_*N_*F_];    // per-expert slabs
__device__ float g_mid2[(size_t)2*N_*F_];     // deep mid2 slabs
__device__ float g_Yc  [(size_t)E_*N_*C_];    // per-slot expert outputs
__device__ float g_Wqkv[C3_*C_];              // transposed [n][k]
__device__ float g_Wt  [WT_TOTAL];            // transposed+rounded weights
__device__ int   g_cnt [E_];
__device__ int   g_tok [E_*N_];
__device__ float g_gw  [E_*N_];
__device__ int   g_slot[2*N_];

// ---------------- helpers ----------------
__device__ __forceinline__ float gelu_f(float z) {
    return 0.5f * z * (1.0f + erff(z * 0.70710678118654752440f));
}

__device__ __forceinline__ float rna_tf32(float f) {
    unsigned r;
    asm("cvt.rna.tf32.f32 %0, %1;" : "=r"(r) : "f"(f));
    return __uint_as_float(r);
}

__device__ __forceinline__ void cpa16(void* smem_dst, const void* gsrc) {
    unsigned d = (unsigned)__cvta_generic_to_shared(smem_dst);
    asm volatile("cp.async.cg.shared.global [%0], [%1], 16;" :: "r"(d), "l"(gsrc));
}

__device__ __forceinline__ void ldsm4(unsigned &r0, unsigned &r1, unsigned &r2, unsigned &r3,
                                      const void* p) {
    unsigned addr = (unsigned)__cvta_generic_to_shared(p);
    asm volatile("ldmatrix.sync.aligned.m8n8.x4.shared.b16 {%0,%1,%2,%3}, [%4];"
        : "=r"(r0), "=r"(r1), "=r"(r2), "=r"(r3) : "r"(addr));
}

__device__ __forceinline__ void mma_tf32(float* c, const unsigned* a,
                                         unsigned b0, unsigned b1) {
    asm volatile("mma.sync.aligned.m16n8k8.row.col.f32.tf32.tf32.f32 "
        "{%0,%1,%2,%3}, {%4,%5,%6,%7}, {%8,%9}, {%0,%1,%2,%3};"
        : "+f"(c[0]), "+f"(c[1]), "+f"(c[2]), "+f"(c[3])
        : "r"(a[0]), "r"(a[1]), "r"(a[2]), "r"(a[3]), "r"(b0), "r"(b1));
}

__device__ __forceinline__ float blockReduceSum256(float v) {
    __shared__ float sh[8];
    int lane = threadIdx.x & 31, w = threadIdx.x >> 5;
    #pragma unroll
    for (int o = 16; o; o >>= 1) v += __shfl_down_sync(0xffffffffu, v, o);
    if (lane == 0) sh[w] = v;
    __syncthreads();
    float r;
    if (w == 0) {
        float t = (lane < 8) ? sh[lane] : 0.f;
        #pragma unroll
        for (int o = 4; o; o >>= 1) t += __shfl_down_sync(0xffffffffu, t, o);
        if (lane == 0) sh[0] = t;
    }
    __syncthreads();
    r = sh[0];
    __syncthreads();
    return r;
}

// ---------------- small setup kernels ----------------
__global__ void zero_cnt_kernel(int* cnt) {
    if (threadIdx.x < E_) cnt[threadIdx.x] = 0;
}

// pack wq,wk,wv (H,C,HS) -> WqkvT[n=3C][k=C], rounded
__global__ void pack_wqkv_kernel(const float* __restrict__ wq,
                                 const float* __restrict__ wk,
                                 const float* __restrict__ wv) {
    int idx = blockIdx.x * 256 + threadIdx.x;
    if (idx >= C_ * C3_) return;
    int col = idx / C_;          // output row (n)
    int c   = idx - col * C_;    // output col (k)
    int which = col / C_;
    int rem   = col - which * C_;
    int h = rem / HS_;
    int d = rem - h * HS_;
    const float* w = (which == 0) ? wq : ((which == 1) ? wk : wv);
    g_Wqkv[idx] = rna_tf32(w[(h * C_ + c) * HS_ + d]);
}

// tiled transpose+round: in [R][Cc] (batched) -> out [Cc][R]
__global__ __launch_bounds__(256) void transpose_round_kernel(
    const float* __restrict__ in, float* __restrict__ out, int R, int Cc)
{
    __shared__ float tile[32][33];
    size_t boff = (size_t)blockIdx.z * R * Cc;
    const float* ip = in + boff;
    float* op = out + boff;
    int x = blockIdx.x * 32 + threadIdx.x;
    int y = blockIdx.y * 32 + threadIdx.y;
    #pragma unroll
    for (int i = 0; i < 32; i += 8)
        tile[threadIdx.y + i][threadIdx.x] = rna_tf32(ip[(size_t)(y + i) * Cc + x]);
    __syncthreads();
    x = blockIdx.y * 32 + threadIdx.x;
    y = blockIdx.x * 32 + threadIdx.y;
    #pragma unroll
    for (int i = 0; i < 32; i += 8)
        op[(size_t)(y + i) * R + x] = tile[threadIdx.x][threadIdx.y + i];
}

// LayerNorm; ROUND_MAIN rounds main output; outR (optional) gets rounded copy
template<bool ROUND_MAIN>
__global__ __launch_bounds__(256) void ln_kernel(const float* __restrict__ in,
                                                 const float* __restrict__ g,
                                                 const float* __restrict__ b,
                                                 float* __restrict__ out,
                                                 float* __restrict__ outR) {
    int row = blockIdx.x;
    const float* p = in + (size_t)row * C_;
    int t = threadIdx.x;
    float x0 = p[t], x1 = p[t + 256], x2 = p[t + 512];
    float mean = blockReduceSum256(x0 + x1 + x2) * (1.0f / C_);
    float d0 = x0 - mean, d1 = x1 - mean, d2 = x2 - mean;
    float var = blockReduceSum256(d0*d0 + d1*d1 + d2*d2) * (1.0f / C_);
    float rstd = rsqrtf(var + 1e-5f);
    float v0 = d0 * rstd * g[t]       + b[t];
    float v1 = d1 * rstd * g[t + 256] + b[t + 256];
    float v2 = d2 * rstd * g[t + 512] + b[t + 512];
    float* o = out + (size_t)row * C_;
    if (ROUND_MAIN) {
        o[t] = rna_tf32(v0); o[t+256] = rna_tf32(v1); o[t+512] = rna_tf32(v2);
    } else {
        o[t] = v0; o[t+256] = v1; o[t+512] = v2;
    }
    if (outR) {
        float* r = outR + (size_t)row * C_;
        r[t] = rna_tf32(v0); r[t+256] = rna_tf32(v1); r[t+512] = rna_tf32(v2);
    }
}

// ---------------- tf32 GEMM body: 128x128x32 tiles, 3-stage ring, B n-major ----------------
// C[m,n] = act(A[m,:] @ Bt[n,:]^T + bias[n]) (+resid); all operands pre-rounded tf32.
// Bt is [Nn][Kk] (n-major). Kk % 32 == 0.
template<bool GATHER, int ACT, bool RESID, bool ROUND>
__device__ __forceinline__ void gemm_body(
    const float* __restrict__ A, int lda,
    const float* __restrict__ Bt,
    const float* __restrict__ bias,
    const float* __restrict__ resid,
    float* __restrict__ Cm, int ldc,
    int M, int Kk,
    const int* __restrict__ rows,
    int m0, int n0)
{
    extern __shared__ float sm[];
    float* sA = sm;                 // [3][128][ST_]
    float* sB = sm + 3*128*ST_;     // [3][128][ST_]
    __shared__ int rIdx[128];

    int tid = threadIdx.x;
    if (GATHER) {
        if (tid < 128) { int m = m0 + tid; rIdx[tid] = rows[(m < M) ? m : (M - 1)]; }
        __syncthreads();
    }

    int ldRow = tid & 127;
    int ldCol = (tid >> 7) * 4;      // {0,4}; covers cols via +8 steps
    int aSrcRow;
    if (GATHER) aSrcRow = rIdx[ldRow];
    else { int gm = m0 + ldRow; aSrcRow = (gm < M) ? gm : (M - 1); }
    const float* aPtr = A + (size_t)aSrcRow * lda;
    const float* bPtr = Bt + (size_t)(n0 + ldRow) * Kk;

    int nTiles = Kk / 32;

    // prologue: tiles 0,1
    #pragma unroll
    for (int s = 0; s < 2; s++) {
        float* dA = sA + (s*128 + ldRow)*ST_ + ldCol;
        float* dB = sB + (s*128 + ldRow)*ST_ + ldCol;
        int k0 = s * 32;
        #pragma unroll
        for (int q = 0; q < 4; q++) {
            cpa16(dA + q*8, aPtr + k0 + ldCol + q*8);
            cpa16(dB + q*8, bPtr + k0 + ldCol + q*8);
        }
        asm volatile("cp.async.commit_group;");
    }

    int wid = tid >> 5, lane = tid & 31;
    int warpM = (wid >> 2) * 64;
    int warpN = (wid & 3) * 32;
    int g  = lane >> 2;
    int tg = lane & 3;
    int rowIn = ((lane >> 3) & 1) * 8 + (lane & 7);
    int colIn = (lane >> 4) * 4;

    float acc[4][4][4];
    #pragma unroll
    for (int i = 0; i < 4; i++)
        #pragma unroll
        for (int j = 0; j < 4; j++)
            #pragma unroll
            for (int r = 0; r < 4; r++) acc[i][j][r] = 0.f;

    for (int t = 0; t < nTiles; t++) {
        asm volatile("cp.async.wait_group 1;");
        __syncthreads();

        int tn = t + 2;
        if (tn < nTiles) {
            int stg = tn % 3;
            int k0 = tn * 32;
            float* dA = sA + (stg*128 + ldRow)*ST_ + ldCol;
            float* dB = sB + (stg*128 + ldRow)*ST_ + ldCol;
            #pragma unroll
            for (int q = 0; q < 4; q++) {
                cpa16(dA + q*8, aPtr + k0 + ldCol + q*8);
                cpa16(dB + q*8, bPtr + k0 + ldCol + q*8);
            }
        }
        asm volatile("cp.async.commit_group;");

        int buf = t % 3;
        const float* Ab = sA + buf*128*ST_;
        const float* Bb = sB + buf*128*ST_;
        #pragma unroll
        for (int s = 0; s < 4; s++) {
            unsigned af[4][4];
            #pragma unroll
            for (int i = 0; i < 4; i++)
                ldsm4(af[i][0], af[i][1], af[i][2], af[i][3],
                      &Ab[(warpM + i*16 + rowIn)*ST_ + s*8 + colIn]);
            unsigned bq[2][4];
            #pragma unroll
            for (int j2 = 0; j2 < 2; j2++)
                ldsm4(bq[j2][0], bq[j2][1], bq[j2][2], bq[j2][3],
                      &Bb[(warpN + j2*16 + rowIn)*ST_ + s*8 + colIn]);
            #pragma unroll
            for (int i = 0; i < 4; i++) {
                mma_tf32(acc[i][0], af[i], bq[0][0], bq[0][2]);
                mma_tf32(acc[i][1], af[i], bq[0][1], bq[0][3]);
                mma_tf32(acc[i][2], af[i], bq[1][0], bq[1][2]);
                mma_tf32(acc[i][3], af[i], bq[1][1], bq[1][3]);
            }
        }
    }

    #pragma unroll
    for (int i = 0; i < 4; i++) {
        int r0 = m0 + warpM + i * 16 + g;
        int r1 = r0 + 8;
        #pragma unroll
        for (int j = 0; j < 4; j++) {
            int col = n0 + warpN + j * 8 + tg * 2;
            float b0 = 0.f, b1 = 0.f;
            if (bias) { b0 = bias[col]; b1 = bias[col + 1]; }
            if (r0 < M) {
                float v0 = acc[i][j][0] + b0;
                float v1 = acc[i][j][1] + b1;
                if (ACT == 1) { v0 = gelu_f(v0); v1 = gelu_f(v1); }
                if (RESID) {
                    v0 += resid[(size_t)r0 * ldc + col];
                    v1 += resid[(size_t)r0 * ldc + col + 1];
                }
                if (ROUND) { v0 = rna_tf32(v0); v1 = rna_tf32(v1); }
                *(float2*)&Cm[(size_t)r0 * ldc + col] = make_float2(v0, v1);
            }
            if (r1 < M) {
                float v2 = acc[i][j][2] + b0;
                float v3 = acc[i][j][3] + b1;
                if (ACT == 1) { v2 = gelu_f(v2); v3 = gelu_f(v3); }
                if (RESID) {
                    v2 += resid[(size_t)r1 * ldc + col];
                    v3 += resid[(size_t)r1 * ldc + col + 1];
                }
                if (ROUND) { v2 = rna_tf32(v2); v3 = rna_tf32(v3); }
                *(float2*)&Cm[(size_t)r1 * ldc + col] = make_float2(v2, v3);
            }
        }
    }
}

// plain GEMM wrapper (QKV, proj)
template<int ACT, bool RESID, bool ROUND>
__global__ __launch_bounds__(256) void tgemm_k(
    const float* __restrict__ A, int lda,
    const float* __restrict__ Bt,
    const float* __restrict__ bias,
    const float* __restrict__ resid,
    float* __restrict__ Cm, int ldc,
    int M, int Kk)
{
    int m0 = blockIdx.y * 128;
    if (m0 >= M) return;
    gemm_body<false, ACT, RESID, ROUND>(A, lda, Bt, bias, resid, Cm, ldc,
                                        M, Kk, nullptr, m0, blockIdx.x * 128);
}

// ---------------- batched expert GEMMs (blockIdx.z = expert) ----------------
template<int MODE>
__global__ __launch_bounds__(256) void egemm_k(
    const float* __restrict__ hA,
    const float* __restrict__ mid1,
    const float* __restrict__ mid2,
    const float* __restrict__ Wt,
    const float* __restrict__ dBias, const float* __restrict__ sBias,
    float* __restrict__ Cout,
    const int* __restrict__ tok, const int* __restrict__ cnt)
{
    int z = blockIdx.z;
    int M = cnt[z];
    int m0 = blockIdx.y * 128;
    if (m0 >= M) return;
    int n0 = blockIdx.x * 128;
    bool deep = (MODE == 1) ? true : (z < 2);

    if (MODE == 0) {
        const float* W  = deep ? Wt + WT_DW1 + (size_t)z * F_ * C_
                               : Wt + WT_SW1 + (size_t)(z - 2) * F_ * C_;
        const float* bs = deep ? dBias + (size_t)z * F_ : sBias + (size_t)(z - 2) * F_;
        float* Cm = Cout + (size_t)z * N_ * F_;
        gemm_body<true, 1, false, true>(hA, C_, W, bs, nullptr, Cm, F_,
                                        M, C_, tok + (size_t)z * N_, m0, n0);
    } else if (MODE == 1) {
        const float* A  = mid1 + (size_t)z * N_ * F_;
        const float* W  = Wt + WT_DW2 + (size_t)z * F_ * F_;
        const float* bs = dBias + (size_t)z * F_;
        float* Cm = Cout + (size_t)z * N_ * F_;
        gemm_body<false, 1, false, true>(A, F_, W, bs, nullptr, Cm, F_,
                                         M, F_, nullptr, m0, n0);
    } else {
        const float* A  = deep ? mid2 + (size_t)z * N_ * F_ : mid1 + (size_t)z * N_ * F_;
        const float* W  = deep ? Wt + WT_DW3 + (size_t)z * C_ * F_
                               : Wt + WT_SW2 + (size_t)(z - 2) * C_ * F_;
        const float* bs = deep ? dBias + (size_t)z * C_ : sBias + (size_t)(z - 2) * C_;
        float* Cm = Cout + (size_t)z * N_ * C_;
        gemm_body<false, 0, false, false>(A, F_, W, bs, nullptr, Cm, C_,
                                          M, F_, nullptr, m0, n0);
    }
}

// ---------------- attention scores (tf32 mma; K loaded n-major directly) ----------------
__global__ __launch_bounds__(256) void attn_scores_tc(const float* __restrict__ qkv,
                                                      float* __restrict__ S) {
    int t0 = blockIdx.y * 128, s0 = blockIdx.x * 128;
    if (s0 > t0) return;
    int bh = blockIdx.z;
    int b = bh / H_, h = bh - b * H_;

    extern __shared__ float sm[];
    float* Qs = sm;              // [128][68]
    float* Ks = sm + 128*68;     // [128 s][68 d]  (n-major)
    int tid = threadIdx.x;

    const float* qbase = qkv + (size_t)(b * T_ + t0) * C3_ + h * HS_;
    const float* kbase = qkv + (size_t)(b * T_ + s0) * C3_ + C_ + h * HS_;
    #pragma unroll
    for (int l = 0; l < 8; l++) {
        int idx = tid + l * 256;
        int r = idx >> 4, q = idx & 15;
        cpa16(&Qs[r*68 + q*4], qbase + (size_t)r * C3_ + q * 4);
        cpa16(&Ks[r*68 + q*4], kbase + (size_t)r * C3_ + q * 4);
    }
    asm volatile("cp.async.commit_group;");
    asm volatile("cp.async.wait_group 0;");
    __syncthreads();

    int wid = tid >> 5, lane = tid & 31;
    int warpM = (wid >> 2) * 64, warpN = (wid & 3) * 32;
    int g = lane >> 2, tg = lane & 3;
    int rowIn = ((lane >> 3) & 1) * 8 + (lane & 7);
    int colIn = (lane >> 4) * 4;

    float acc[4][4][4];
    #pragma unroll
    for (int i = 0; i < 4; i++)
        #pragma unroll
        for (int j = 0; j < 4; j++)
            #pragma unroll
            for (int r = 0; r < 4; r++) acc[i][j][r] = 0.f;

    #pragma unroll
    for (int ks = 0; ks < 8; ks++) {
        unsigned af[4][4];
        #pragma unroll
        for (int i = 0; i < 4; i++)
            ldsm4(af[i][0], af[i][1], af[i][2], af[i][3],
                  &Qs[(warpM + i*16 + rowIn)*68 + ks*8 + colIn]);
        unsigned bq[2][4];
        #pragma unroll
        for (int j2 = 0; j2 < 2; j2++)
            ldsm4(bq[j2][0], bq[j2][1], bq[j2][2], bq[j2][3],
                  &Ks[(warpN + j2*16 + rowIn)*68 + ks*8 + colIn]);
        #pragma unroll
        for (int i = 0; i < 4; i++) {
            mma_tf32(acc[i][0], af[i], bq[0][0], bq[0][2]);
            mma_tf32(acc[i][1], af[i], bq[0][1], bq[0][3]);
            mma_tf32(acc[i][2], af[i], bq[1][0], bq[1][2]);
            mma_tf32(acc[i][3], af[i], bq[1][1], bq[1][3]);
        }
    }

    const float scale = 0.03608439182435161f;   // 768^-0.5
    float* op = S + ((size_t)bh * T_ + t0) * T_ + s0;
    #pragma unroll
    for (int i = 0; i < 4; i++) {
        int r0 = warpM + i * 16 + g;
        int r1 = r0 + 8;
        #pragma unroll
        for (int j = 0; j < 4; j++) {
            int col = warpN + j * 8 + tg * 2;
            *(float2*)&op[(size_t)r0 * T_ + col] =
                make_float2(acc[i][j][0] * scale, acc[i][j][1] * scale);
            *(float2*)&op[(size_t)r1 * T_ + col] =
                make_float2(acc[i][j][2] * scale, acc[i][j][3] * scale);
        }
    }
}

// ---------------- causal softmax (in place, rounds P, zero-fill to tile edge) ----------------
__global__ __launch_bounds__(128) void softmax_causal_kernel(float* __restrict__ S) {
    int row = blockIdx.x;
    int t = row & (T_ - 1);
    float* p = S + (size_t)row * T_;
    int len = t + 1;
    int end = ((t >> 7) + 1) << 7;
    int tid = threadIdx.x;
    __shared__ float sh[4];

    float mx = -1e30f;
    for (int s = tid; s < len; s += 128) mx = fmaxf(mx, p[s]);
    #pragma unroll
    for (int o = 16; o; o >>= 1) mx = fmaxf(mx, __shfl_down_sync(0xffffffffu, mx, o));
    if ((tid & 31) == 0) sh[tid >> 5] = mx;
    __syncthreads();
    mx = fmaxf(fmaxf(sh[0], sh[1]), fmaxf(sh[2], sh[3]));
    __syncthreads();

    float sum = 0.f;
    for (int s = tid; s < len; s += 128) { float e = __expf(p[s] - mx); p[s] = e; sum += e; }
    #pragma unroll
    for (int o = 16; o; o >>= 1) sum += __shfl_down_sync(0xffffffffu, sum, o);
    if ((tid & 31) == 0) sh[tid >> 5] = sum;
    __syncthreads();
    sum = sh[0] + sh[1] + sh[2] + sh[3];
    float inv = 1.f / sum;
    for (int s = tid; s < len; s += 128) p[s] = rna_tf32(p[s] * inv);
    for (int s = len + tid; s < end; s += 128) p[s] = 0.f;
}

// ---------------- PV (tf32 mma, 6-stage ring, 2 tiles/barrier) ----------------
__global__ __launch_bounds__(256) void attn_pv_tc(const float* __restrict__ qkv,
                                                  const float* __restrict__ P,
                                                  float* __restrict__ O) {
    int t0 = blockIdx.x * 128;
    int bh = blockIdx.y;
    int b = bh / H_, h = bh - b * H_;

    extern __shared__ float sm[];
    float* sA = sm;                 // [6][128][20]
    float* sB = sm + 6*128*20;      // [6][16][72]

    int tid = threadIdx.x;
    const float* aPtr = P + ((size_t)bh * T_ + t0) * T_;
    const float* vbase = qkv + (size_t)(b * T_) * C3_ + 2 * C_ + h * HS_;

    int aRow = tid & 127;
    int aColQ = (tid >> 7) * 8;
    int bK = tid >> 4;
    int bN = (tid & 15) * 4;

    int nTiles = (t0 + 128) / 16;

    #pragma unroll
    for (int s = 0; s < 4; s++) {
        int k0 = s * 16;
        cpa16(&sA[((s*128) + aRow)*20 + aColQ],     aPtr + (size_t)aRow * T_ + k0 + aColQ);
        cpa16(&sA[((s*128) + aRow)*20 + aColQ + 4], aPtr + (size_t)aRow * T_ + k0 + aColQ + 4);
        cpa16(&sB[((s*16) + bK)*72 + bN], vbase + (size_t)(k0 + bK) * C3_ + bN);
        asm volatile("cp.async.commit_group;");
    }

    int wid = tid >> 5, lane = tid & 31;
    int warpM = (wid >> 1) * 32;
    int warpN = (wid & 1) * 32;
    int g = lane >> 2, tg = lane & 3;
    int rowIn = ((lane >> 3) & 1) * 8 + (lane & 7);
    int colIn = (lane >> 4) * 4;

    float acc[2][4][4];
    #pragma unroll
    for (int i = 0; i < 2; i++)
        #pragma unroll
        for (int j = 0; j < 4; j++)
            #pragma unroll
            for (int r = 0; r < 4; r++) acc[i][j][r] = 0.f;

    for (int t = 0; t < nTiles; t += 2) {
        asm volatile("cp.async.wait_group 2;");
        __syncthreads();

        #pragma unroll
        for (int u = 4; u < 6; u++) {
            int tn = t + u;
            if (tn < nTiles) {
                int stg = tn % 6;
                int k0 = tn * 16;
                cpa16(&sA[((stg*128) + aRow)*20 + aColQ],     aPtr + (size_t)aRow * T_ + k0 + aColQ);
                cpa16(&sA[((stg*128) + aRow)*20 + aColQ + 4], aPtr + (size_t)aRow * T_ + k0 + aColQ + 4);
                cpa16(&sB[((stg*16) + bK)*72 + bN], vbase + (size_t)(k0 + bK) * C3_ + bN);
            }
            asm volatile("cp.async.commit_group;");
        }

        #pragma unroll
        for (int u = 0; u < 2; u++) {
            int buf = (t + u) % 6;
            const float* Ab = sA + buf*128*20;
            const float* Bb = sB + buf*16*72;
            #pragma unroll
            for (int s = 0; s < 2; s++) {
                unsigned af[2][4];
                #pragma unroll
                for (int i = 0; i < 2; i++)
                    ldsm4(af[i][0], af[i][1], af[i][2], af[i][3],
                          &Ab[(warpM + i*16 + rowIn)*20 + s*8 + colIn]);
                unsigned bf[4][2];
                #pragma unroll
                for (int j = 0; j < 4; j++) {
                    int col = warpN + j*8 + g;
                    bf[j][0] = __float_as_uint(Bb[(s*8 + tg)*72 + col]);
                    bf[j][1] = __float_as_uint(Bb[(s*8 + tg + 4)*72 + col]);
                }
                #pragma unroll
                for (int i = 0; i < 2; i++)
                    #pragma unroll
                    for (int j = 0; j < 4; j++)
                        mma_tf32(acc[i][j], af[i], bf[j][0], bf[j][1]);
            }
        }
    }

    #pragma unroll
    for (int i = 0; i < 2; i++) {
        int r0 = warpM + i * 16 + g;
        int r1 = r0 + 8;
        #pragma unroll
        for (int j = 0; j < 4; j++) {
            int col = h * HS_ + warpN + j * 8 + tg * 2;
            *(float2*)&O[(size_t)(b * T_ + t0 + r0) * C_ + col] =
                make_float2(rna_tf32(acc[i][j][0]), rna_tf32(acc[i][j][1]));
            *(float2*)&O[(size_t)(b * T_ + t0 + r1) * C_ + col] =
                make_float2(rna_tf32(acc[i][j][2]), rna_tf32(acc[i][j][3]));
        }
    }
}

// ---------------- router: noisy top-2 + assignment + slot table ----------------
__global__ __launch_bounds__(256) void router_kernel(
    const float* __restrict__ h2,
    const float* __restrict__ wr, const float* __restrict__ br,
    const float* __restrict__ wn, const float* __restrict__ bn,
    const float* __restrict__ noise, const float* __restrict__ temp_p,
    int* __restrict__ cnt, int* __restrict__ tok, float* __restrict__ gw,
    int* __restrict__ slot)
{
    int n = blockIdx.x * 8 + (threadIdx.x >> 5);
    if (n >= N_) return;
    int lane = threadIdx.x & 31;
    float ar[E_] = {}, an[E_] = {};
    const float* hp = h2 + (size_t)n * C_;
    for (int c = lane; c < C_; c += 32) {
        float hv = hp[c];
        const float* wrp = wr + c * E_;
        const float* wnp = wn + c * E_;
        #pragma unroll
        for (int e = 0; e < E_; e++) {
            ar[e] = fmaf(hv, wrp[e], ar[e]);
            an[e] = fmaf(hv, wnp[e], an[e]);
        }
    }
    #pragma unroll
    for (int e = 0; e < E_; e++) {
        #pragma unroll
        for (int o = 16; o; o >>= 1) {
            ar[e] += __shfl_down_sync(0xffffffffu, ar[e], o);
            an[e] += __shfl_down_sync(0xffffffffu, an[e], o);
        }
    }
    if (lane == 0) {
        float t = fminf(fmaxf(*temp_p, 0.5f), 2.0f);
        float noisy[E_];
        #pragma unroll
        for (int e = 0; e < E_; e++) {
            float logit = ar[e] + br[e];
            float z = an[e] + bn[e];
            float sp = fmaxf(z, 0.f) + log1pf(expf(-fabsf(z)));
            noisy[e] = logit + t * noise[(size_t)n * E_ + e] * sp;
        }
        int i1 = 0;
        #pragma unroll
        for (int e = 1; e < E_; e++) if (noisy[e] > noisy[i1]) i1 = e;
        int i2 = -1;
        #pragma unroll
        for (int e = 0; e < E_; e++)
            if (e != i1 && (i2 < 0 || noisy[e] > noisy[i2])) i2 = e;
        float m = fmaxf(noisy[i1], noisy[i2]);
        float e1 = __expf(noisy[i1] - m), e2 = __expf(noisy[i2] - m);
        float inv = 1.f / (e1 + e2);
        int p1 = atomicAdd(&cnt[i1], 1); tok[i1 * N_ + p1] = n; gw[i1 * N_ + p1] = e1 * inv;
        int p2 = atomicAdd(&cnt[i2], 1); tok[i2 * N_ + p2] = n; gw[i2 * N_ + p2] = e2 * inv;
        slot[2 * n]     = i1 * N_ + p1;
        slot[2 * n + 1] = i2 * N_ + p2;
    }
}

// ---------------- slot epilogue: Yc[s] = gate * LN(h2[n] + Yc[s]) ----------------
__global__ __launch_bounds__(256) void expert_epi_slots(
    float* __restrict__ Yc, const float* __restrict__ h2,
    const int* __restrict__ tok, const float* __restrict__ gw,
    const int* __restrict__ slot,
    const float* __restrict__ dlg, const float* __restrict__ dlb,
    const float* __restrict__ slg, const float* __restrict__ slb)
{
    int s = slot[blockIdx.x];
    int z = s >> 13;            // /N_
    bool deep = z < 2;
    const float* lg = deep ? dlg + (size_t)z * C_ : slg + (size_t)(z - 2) * C_;
    const float* lb = deep ? dlb + (size_t)z * C_ : slb + (size_t)(z - 2) * C_;
    int n = tok[s];
    float g = gw[s];
    float* yp = Yc + (size_t)s * C_;
    const float* hp = h2 + (size_t)n * C_;
    int t = threadIdx.x;
    float z0 = hp[t]       + yp[t];
    float z1 = hp[t + 256] + yp[t + 256];
    float z2 = hp[t + 512] + yp[t + 512];
    float mean = blockReduceSum256(z0 + z1 + z2) * (1.0f / C_);
    float d0 = z0 - mean, d1 = z1 - mean, d2 = z2 - mean;
    float var = blockReduceSum256(d0*d0 + d1*d1 + d2*d2) * (1.0f / C_);
    float rstd = rsqrtf(var + 1e-5f);
    yp[t]       = g * (d0 * rstd * lg[t]       + lb[t]);
    yp[t + 256] = g * (d1 * rstd * lg[t + 256] + lb[t + 256]);
    yp[t + 512] = g * (d2 * rstd * lg[t + 512] + lb[t + 512]);
}

// ---------------- final combine: out[n] += Yc[slot0] + Yc[slot1] ----------------
__global__ __launch_bounds__(256) void combine_kernel(
    const float* __restrict__ Yc, const int* __restrict__ slot,
    float* __restrict__ out)
{
    int n = blockIdx.x;
    const float* a = Yc + (size_t)slot[2 * n] * C_;
    const float* b = Yc + (size_t)slot[2 * n + 1] * C_;
    float* op = out + (size_t)n * C_;
    int t = threadIdx.x;
    op[t]       += a[t]       + b[t];
    op[t + 256] += a[t + 256] + b[t + 256];
    op[t + 512] += a[t + 512] + b[t + 512];
}

// ---------------- launch ----------------
extern "C" void kernel_launch(void* const* d_in, const int* in_sizes, int n_in,
                              void* d_out, int out_size) {
    const float* x         = (const float*)d_in[0];
    const float* rnoise    = (const float*)d_in[1];
    const float* wq        = (const float*)d_in[2];
    const float* wk        = (const float*)d_in[3];
    const float* wv        = (const float*)d_in[4];
    const float* w_proj    = (const float*)d_in[5];
    const float* b_proj    = (const float*)d_in[6];
    const float* ln1_g     = (const float*)d_in[7];
    const float* ln1_b     = (const float*)d_in[8];
    const float* ln2_g     = (const float*)d_in[9];
    const float* ln2_b     = (const float*)d_in[10];
    const float* w_route   = (const float*)d_in[11];
    const float* b_route   = (const float*)d_in[12];
    const float* w_noise   = (const float*)d_in[13];
    const float* b_noise   = (const float*)d_in[14];
    const float* temp      = (const float*)d_in[15];
    const float* deep_w1   = (const float*)d_in[16];
    const float* deep_b1   = (const float*)d_in[17];
    const float* deep_w2   = (const float*)d_in[18];
    const float* deep_b2   = (const float*)d_in[19];
    const float* deep_w3   = (const float*)d_in[20];
    const float* deep_b3   = (const float*)d_in[21];
    const float* deep_ln_g = (const float*)d_in[22];
    const float* deep_ln_b = (const float*)d_in[23];
    const float* simple_w1   = (const float*)d_in[24];
    const float* simple_b1   = (const float*)d_in[25];
    const float* simple_w2   = (const float*)d_in[26];
    const float* simple_b2   = (const float*)d_in[27];
    const float* simple_ln_g = (const float*)d_in[28];
    const float* simple_ln_b = (const float*)d_in[29];

    float* out = (float*)d_out;

    float *h1, *qkv, *S, *o, *h2, *mid1, *mid2, *Yc, *Wqkv, *Wt, *gw;
    int *cnt, *tok, *slot;
    cudaGetSymbolAddress((void**)&h1,   g_h1);
    cudaGetSymbolAddress((void**)&qkv,  g_qkv);
    cudaGetSymbolAddress((void**)&S,    g_S);
    cudaGetSymbolAddress((void**)&o,    g_o);
    cudaGetSymbolAddress((void**)&h2,   g_h2);
    cudaGetSymbolAddress((void**)&mid1, g_mid1);
    cudaGetSymbolAddress((void**)&mid2, g_mid2);
    cudaGetSymbolAddress((void**)&Yc,   g_Yc);
    cudaGetSymbolAddress((void**)&Wqkv, g_Wqkv);
    cudaGetSymbolAddress((void**)&Wt,   g_Wt);
    cudaGetSymbolAddress((void**)&cnt,  g_cnt);
    cudaGetSymbolAddress((void**)&tok,  g_tok);
    cudaGetSymbolAddress((void**)&gw,   g_gw);
    cudaGetSymbolAddress((void**)&slot, g_slot);

    // raise dynamic smem limits (idempotent)
    cudaFuncSetAttribute((const void*)tgemm_k<0,false,true>, cudaFuncAttributeMaxDynamicSharedMemorySize, TG_SMEM);
    cudaFuncSetAttribute((const void*)tgemm_k<0,true,false>, cudaFuncAttributeMaxDynamicSharedMemorySize, TG_SMEM);
    cudaFuncSetAttribute((const void*)egemm_k<0>, cudaFuncAttributeMaxDynamicSharedMemorySize, TG_SMEM);
    cudaFuncSetAttribute((const void*)egemm_k<1>, cudaFuncAttributeMaxDynamicSharedMemorySize, TG_SMEM);
    cudaFuncSetAttribute((const void*)egemm_k<2>, cudaFuncAttributeMaxDynamicSharedMemorySize, TG_SMEM);
    cudaFuncSetAttribute((const void*)attn_scores_tc, cudaFuncAttributeMaxDynamicSharedMemorySize, SC_SMEM);
    cudaFuncSetAttribute((const void*)attn_pv_tc,     cudaFuncAttributeMaxDynamicSharedMemorySize, PV_SMEM);

    zero_cnt_kernel<<<1, 32>>>(cnt);
    pack_wqkv_kernel<<<(C_ * C3_ + 255) / 256, 256>>>(wq, wk, wv);

    // transpose+round weights to n-major tf32
    dim3 tb(32, 8);
    transpose_round_kernel<<<dim3(C_/32, C_/32, 1), tb>>>(w_proj,    Wt + WT_PROJ, C_, C_);
    transpose_round_kernel<<<dim3(F_/32, C_/32, 2), tb>>>(deep_w1,   Wt + WT_DW1,  C_, F_);
    transpose_round_kernel<<<dim3(F_/32, F_/32, 2), tb>>>(deep_w2,   Wt + WT_DW2,  F_, F_);
    transpose_round_kernel<<<dim3(C_/32, F_/32, 2), tb>>>(deep_w3,   Wt + WT_DW3,  F_, C_);
    transpose_round_kernel<<<dim3(F_/32, C_/32, 6), tb>>>(simple_w1, Wt + WT_SW1,  C_, F_);
    transpose_round_kernel<<<dim3(C_/32, F_/32, 6), tb>>>(simple_w2, Wt + WT_SW2,  F_, C_);

    // ln1 -> h1 (rounded) ; qkv = h1 @ Wqkv^T (rounded out)
    ln_kernel<true><<<N_, 256>>>(x, ln1_g, ln1_b, h1, nullptr);
    tgemm_k<0, false, true><<<dim3(C3_ / 128, N_ / 128), 256, TG_SMEM>>>(
        h1, C_, Wqkv, nullptr, nullptr, qkv, C3_, N_, C_);

    // attention (tensor core)
    attn_scores_tc<<<dim3(T_ / 128, T_ / 128, BH_), 256, SC_SMEM>>>(qkv, S);
    softmax_causal_kernel<<<BH_ * T_, 128>>>(S);
    attn_pv_tc<<<dim3(T_ / 128, BH_), 256, PV_SMEM>>>(qkv, S, o);

    // out = x + o @ w_proj + b_proj
    tgemm_k<0, true, false><<<dim3(C_ / 128, N_ / 128), 256, TG_SMEM>>>(
        o, C_, Wt + WT_PROJ, b_proj, x, out, C_, N_, C_);

    // ln2 -> h2 (exact) + h2r (rounded, reuses h1) ; router
    ln_kernel<false><<<N_, 256>>>(out, ln2_g, ln2_b, h2, h1);
    router_kernel<<<N_ / 8, 256>>>(h2, w_route, b_route, w_noise, b_noise,
                                   rnoise, temp, cnt, tok, gw, slot);

    // experts, batched across blockIdx.z
    egemm_k<0><<<dim3(F_ / 128, N_ / 128, E_), 256, TG_SMEM>>>(
        h1, mid1, mid2, Wt, deep_b1, simple_b1, mid1, tok, cnt);
    egemm_k<1><<<dim3(F_ / 128, N_ / 128, 2), 256, TG_SMEM>>>(
        h1, mid1, mid2, Wt, deep_b2, nullptr, mid2, tok, cnt);
    egemm_k<2><<<dim3(C_ / 128, N_ / 128, E_), 256, TG_SMEM>>>(
        h1, mid1, mid2, Wt, deep_b3, simple_b2, Yc, tok, cnt);

    // slot epilogue (exactly 2N active blocks) + final combine
    expert_epi_slots<<<2 * N_, 256>>>(Yc, h2, tok, gw, slot,
                                      deep_ln_g, deep_ln_b,
                                      simple_ln_g, simple_ln_b);
    combine_kernel<<<N_, 256>>>(Yc, slot, out);
}

// round 17
// speedup vs baseline: 1.8126x; 1.8126x over previous
#include <cuda_runtime.h>
#include <cuda_bf16.h>
#include <math.h>

// ---------------- problem constants ----------------
#define B_   8
#define T_   1024
#define C_   768
#define H_   12
#define HS_  64
#define E_   8
#define F_   3072
#define N_   (B_*T_)     // 8192 tokens
#define BH_  (B_*H_)     // 96
#define C3_  (3*C_)      // 2304

#define STB_ 40          // bf16 smem row stride for 32-deep GEMM tiles (80B, 16B-mult)
#define GST_ 5           // GEMM pipeline stages

// dynamic smem sizes (bytes)
#define TG_SMEM  (GST_*128*STB_*2*2)         // 102400
#define SC_SMEM  (2*128*72*2)                // 36864
#define PV_SMEM  (4*128*STB_*2 + 4*32*72*2)  // 40960+18432 = 59392

// transposed-weight slab offsets (bf16 elements)
#define WT_PROJ  0
#define WT_DW1   (WT_PROJ + C_*C_)
#define WT_DW2   (WT_DW1 + 2*C_*F_)
#define WT_DW3   (WT_DW2 + 2*F_*F_)
#define WT_SW1   (WT_DW3 + 2*F_*C_)
#define WT_SW2   (WT_SW1 + 6*C_*F_)
#define WT_TOTAL (WT_SW2 + 6*F_*C_)

// ---------------- scratch (device globals; no allocation) ----------------
__device__ __nv_bfloat16 g_h1  [N_*C_];              // h1 bf16, later h2r bf16
__device__ __nv_bfloat16 g_qkv [N_*C3_];
__device__ float         g_S   [(size_t)BH_*T_*T_];  // raw scores fp32
__device__ __nv_bfloat16 g_P   [(size_t)BH_*T_*T_];  // probabilities bf16
__device__ __nv_bfloat16 g_o   [N_*C_];
__device__ float         g_h2  [N_*C_];              // exact h2
__device__ __nv_bfloat16 g_mid1[(size_t)E_*N_*F_];
__device__ __nv_bfloat16 g_mid2[(size_t)2*N_*F_];
__device__ float         g_Yc  [(size_t)E_*N_*C_];
__device__ __nv_bfloat16 g_Wqkv[C3_*C_];             // n-major [n][k]
__device__ __nv_bfloat16 g_Wt  [WT_TOTAL];           // n-major bf16 weights
__device__ int   g_cnt [E_];
__device__ int   g_tok [E_*N_];
__device__ float g_gw  [E_*N_];
__device__ int   g_slot[2*N_];

// ---------------- helpers ----------------
__device__ __forceinline__ float gelu_f(float z) {
    return 0.5f * z * (1.0f + erff(z * 0.70710678118654752440f));
}

__device__ __forceinline__ void cpa16(void* smem_dst, const void* gsrc) {
    unsigned d = (unsigned)__cvta_generic_to_shared(smem_dst);
    asm volatile("cp.async.cg.shared.global [%0], [%1], 16;" :: "r"(d), "l"(gsrc));
}

__device__ __forceinline__ void ldsm4(unsigned &r0, unsigned &r1, unsigned &r2, unsigned &r3,
                                      const void* p) {
    unsigned addr = (unsigned)__cvta_generic_to_shared(p);
    asm volatile("ldmatrix.sync.aligned.m8n8.x4.shared.b16 {%0,%1,%2,%3}, [%4];"
        : "=r"(r0), "=r"(r1), "=r"(r2), "=r"(r3) : "r"(addr));
}

__device__ __forceinline__ void ldsm4t(unsigned &r0, unsigned &r1, unsigned &r2, unsigned &r3,
                                       const void* p) {
    unsigned addr = (unsigned)__cvta_generic_to_shared(p);
    asm volatile("ldmatrix.sync.aligned.m8n8.x4.trans.shared.b16 {%0,%1,%2,%3}, [%4];"
        : "=r"(r0), "=r"(r1), "=r"(r2), "=r"(r3) : "r"(addr));
}

__device__ __forceinline__ void mma_bf16(float* c, const unsigned* a,
                                         unsigned b0, unsigned b1) {
    asm volatile("mma.sync.aligned.m16n8k16.row.col.f32.bf16.bf16.f32 "
        "{%0,%1,%2,%3}, {%4,%5,%6,%7}, {%8,%9}, {%0,%1,%2,%3};"
        : "+f"(c[0]), "+f"(c[1]), "+f"(c[2]), "+f"(c[3])
        : "r"(a[0]), "r"(a[1]), "r"(a[2]), "r"(a[3]), "r"(b0), "r"(b1));
}

__device__ __forceinline__ float blockReduceSum256(float v) {
    __shared__ float sh[8];
    int lane = threadIdx.x & 31, w = threadIdx.x >> 5;
    #pragma unroll
    for (int o = 16; o; o >>= 1) v += __shfl_down_sync(0xffffffffu, v, o);
    if (lane == 0) sh[w] = v;
    __syncthreads();
    float r;
    if (w == 0) {
        float t = (lane < 8) ? sh[lane] : 0.f;
        #pragma unroll
        for (int o = 4; o; o >>= 1) t += __shfl_down_sync(0xffffffffu, t, o);
        if (lane == 0) sh[0] = t;
    }
    __syncthreads();
    r = sh[0];
    __syncthreads();
    return r;
}

// ---------------- small setup kernels ----------------
__global__ void zero_cnt_kernel(int* cnt) {
    if (threadIdx.x < E_) cnt[threadIdx.x] = 0;
}

// pack wq,wk,wv (H,C,HS) -> WqkvT[n=3C][k=C], bf16
__global__ void pack_wqkv_kernel(const float* __restrict__ wq,
                                 const float* __restrict__ wk,
                                 const float* __restrict__ wv) {
    int idx = blockIdx.x * 256 + threadIdx.x;
    if (idx >= C_ * C3_) return;
    int col = idx / C_;          // n
    int c   = idx - col * C_;    // k
    int which = col / C_;
    int rem   = col - which * C_;
    int h = rem / HS_;
    int d = rem - h * HS_;
    const float* w = (which == 0) ? wq : ((which == 1) ? wk : wv);
    g_Wqkv[idx] = __float2bfloat16_rn(w[(h * C_ + c) * HS_ + d]);
}

// tiled transpose: fp32 [R][Cc] (batched) -> bf16 [Cc][R]
__global__ __launch_bounds__(256) void transpose_bf16_kernel(
    const float* __restrict__ in, __nv_bfloat16* __restrict__ out, int R, int Cc)
{
    __shared__ float tile[32][33];
    size_t boff = (size_t)blockIdx.z * R * Cc;
    const float* ip = in + boff;
    __nv_bfloat16* op = out + boff;
    int x = blockIdx.x * 32 + threadIdx.x;
    int y = blockIdx.y * 32 + threadIdx.y;
    #pragma unroll
    for (int i = 0; i < 32; i += 8)
        tile[threadIdx.y + i][threadIdx.x] = ip[(size_t)(y + i) * Cc + x];
    __syncthreads();
    x = blockIdx.y * 32 + threadIdx.x;
    y = blockIdx.x * 32 + threadIdx.y;
    #pragma unroll
    for (int i = 0; i < 32; i += 8)
        op[(size_t)(y + i) * R + x] = __float2bfloat16_rn(tile[threadIdx.x][threadIdx.y + i]);
}

// LayerNorm: optional fp32 out, optional bf16 out
__global__ __launch_bounds__(256) void ln_kernel(const float* __restrict__ in,
                                                 const float* __restrict__ g,
                                                 const float* __restrict__ b,
                                                 float* __restrict__ outF,
                                                 __nv_bfloat16* __restrict__ outB) {
    int row = blockIdx.x;
    const float* p = in + (size_t)row * C_;
    int t = threadIdx.x;
    float x0 = p[t], x1 = p[t + 256], x2 = p[t + 512];
    float mean = blockReduceSum256(x0 + x1 + x2) * (1.0f / C_);
    float d0 = x0 - mean, d1 = x1 - mean, d2 = x2 - mean;
    float var = blockReduceSum256(d0*d0 + d1*d1 + d2*d2) * (1.0f / C_);
    float rstd = rsqrtf(var + 1e-5f);
    float v0 = d0 * rstd * g[t]       + b[t];
    float v1 = d1 * rstd * g[t + 256] + b[t + 256];
    float v2 = d2 * rstd * g[t + 512] + b[t + 512];
    if (outF) {
        float* o = outF + (size_t)row * C_;
        o[t] = v0; o[t+256] = v1; o[t+512] = v2;
    }
    if (outB) {
        __nv_bfloat16* r = outB + (size_t)row * C_;
        r[t]       = __float2bfloat16_rn(v0);
        r[t + 256] = __float2bfloat16_rn(v1);
        r[t + 512] = __float2bfloat16_rn(v2);
    }
}

// ---------------- bf16 GEMM body: 128x128x32 tiles, 5-stage ring ----------------
// C[m,n] = act(A[m,:] @ Bt[n,:]^T + bias[n]) (+resid)
// A bf16 [M][lda], Bt bf16 [Nn][Kk] n-major. Kk % 32 == 0.
// OUTBF: 1 -> bf16 output, 0 -> fp32 output.
template<bool GATHER, int ACT, bool RESID, int OUTBF>
__device__ __forceinline__ void gemm_body(
    const __nv_bfloat16* __restrict__ A, int lda,
    const __nv_bfloat16* __restrict__ Bt,
    const float* __restrict__ bias,
    const float* __restrict__ resid,
    void* __restrict__ Cm, int ldc,
    int M, int Kk,
    const int* __restrict__ rows,
    int m0, int n0)
{
    extern __shared__ char smraw[];
    __nv_bfloat16* sA = (__nv_bfloat16*)smraw;          // [GST_][128][STB_]
    __nv_bfloat16* sB = sA + GST_*128*STB_;             // [GST_][128][STB_]
    __shared__ int rIdx[128];

    int tid = threadIdx.x;
    if (GATHER) {
        if (tid < 128) { int m = m0 + tid; rIdx[tid] = rows[(m < M) ? m : (M - 1)]; }
        __syncthreads();
    }

    int ldRow = tid & 127;
    int ldCol = (tid >> 7) * 16;     // bf16 units; two cpa16 at +0,+8
    int aSrcRow;
    if (GATHER) aSrcRow = rIdx[ldRow];
    else { int gm = m0 + ldRow; aSrcRow = (gm < M) ? gm : (M - 1); }
    const __nv_bfloat16* aPtr = A + (size_t)aSrcRow * lda;
    const __nv_bfloat16* bPtr = Bt + (size_t)(n0 + ldRow) * Kk;

    int nTiles = Kk / 32;

    // prologue: tiles 0..3
    #pragma unroll
    for (int s = 0; s < 4; s++) {
        int k0 = s * 32;
        __nv_bfloat16* dA = sA + (s*128 + ldRow)*STB_ + ldCol;
        __nv_bfloat16* dB = sB + (s*128 + ldRow)*STB_ + ldCol;
        cpa16(dA,     aPtr + k0 + ldCol);
        cpa16(dA + 8, aPtr + k0 + ldCol + 8);
        cpa16(dB,     bPtr + k0 + ldCol);
        cpa16(dB + 8, bPtr + k0 + ldCol + 8);
        asm volatile("cp.async.commit_group;");
    }

    int wid = tid >> 5, lane = tid & 31;
    int warpM = (wid >> 2) * 64;
    int warpN = (wid & 3) * 32;
    int g  = lane >> 2;
    int tg = lane & 3;
    int rowIn = ((lane >> 3) & 1) * 8 + (lane & 7);
    int colIn = (lane >> 4) * 8;     // bf16 units (16B chunk)

    float acc[4][4][4];
    #pragma unroll
    for (int i = 0; i < 4; i++)
        #pragma unroll
        for (int j = 0; j < 4; j++)
            #pragma unroll
            for (int r = 0; r < 4; r++) acc[i][j][r] = 0.f;

    for (int t = 0; t < nTiles; t++) {
        asm volatile("cp.async.wait_group 3;");
        __syncthreads();

        int tn = t + 4;
        if (tn < nTiles) {
            int stg = tn % GST_;
            int k0 = tn * 32;
            __nv_bfloat16* dA = sA + (stg*128 + ldRow)*STB_ + ldCol;
            __nv_bfloat16* dB = sB + (stg*128 + ldRow)*STB_ + ldCol;
            cpa16(dA,     aPtr + k0 + ldCol);
            cpa16(dA + 8, aPtr + k0 + ldCol + 8);
            cpa16(dB,     bPtr + k0 + ldCol);
            cpa16(dB + 8, bPtr + k0 + ldCol + 8);
        }
        asm volatile("cp.async.commit_group;");

        int buf = t % GST_;
        const __nv_bfloat16* Ab = sA + buf*128*STB_;
        const __nv_bfloat16* Bb = sB + buf*128*STB_;
        #pragma unroll
        for (int s = 0; s < 2; s++) {          // two k16 steps
            unsigned af[4][4];
            #pragma unroll
            for (int i = 0; i < 4; i++)
                ldsm4(af[i][0], af[i][1], af[i][2], af[i][3],
                      &Ab[(warpM + i*16 + rowIn)*STB_ + s*16 + colIn]);
            unsigned bq[2][4];
            #pragma unroll
            for (int j2 = 0; j2 < 2; j2++)
                ldsm4(bq[j2][0], bq[j2][1], bq[j2][2], bq[j2][3],
                      &Bb[(warpN + j2*16 + rowIn)*STB_ + s*16 + colIn]);
            #pragma unroll
            for (int i = 0; i < 4; i++) {
                mma_bf16(acc[i][0], af[i], bq[0][0], bq[0][2]);
                mma_bf16(acc[i][1], af[i], bq[0][1], bq[0][3]);
                mma_bf16(acc[i][2], af[i], bq[1][0], bq[1][2]);
                mma_bf16(acc[i][3], af[i], bq[1][1], bq[1][3]);
            }
        }
    }

    // epilogue
    #pragma unroll
    for (int i = 0; i < 4; i++) {
        int r0 = m0 + warpM + i * 16 + g;
        int r1 = r0 + 8;
        #pragma unroll
        for (int j = 0; j < 4; j++) {
            int col = n0 + warpN + j * 8 + tg * 2;
            float b0 = 0.f, b1 = 0.f;
            if (bias) { b0 = bias[col]; b1 = bias[col + 1]; }
            float v0 = acc[i][j][0] + b0, v1 = acc[i][j][1] + b1;
            float v2 = acc[i][j][2] + b0, v3 = acc[i][j][3] + b1;
            if (ACT == 1) { v0 = gelu_f(v0); v1 = gelu_f(v1); v2 = gelu_f(v2); v3 = gelu_f(v3); }
            if (r0 < M) {
                if (RESID) {
                    v0 += resid[(size_t)r0 * ldc + col];
                    v1 += resid[(size_t)r0 * ldc + col + 1];
                }
                if (OUTBF) {
                    __nv_bfloat162 pr; pr.x = __float2bfloat16_rn(v0); pr.y = __float2bfloat16_rn(v1);
                    *(__nv_bfloat162*)&((__nv_bfloat16*)Cm)[(size_t)r0 * ldc + col] = pr;
                } else {
                    *(float2*)&((float*)Cm)[(size_t)r0 * ldc + col] = make_float2(v0, v1);
                }
            }
            if (r1 < M) {
                if (RESID) {
                    v2 += resid[(size_t)r1 * ldc + col];
                    v3 += resid[(size_t)r1 * ldc + col + 1];
                }
                if (OUTBF) {
                    __nv_bfloat162 pr; pr.x = __float2bfloat16_rn(v2); pr.y = __float2bfloat16_rn(v3);
                    *(__nv_bfloat162*)&((__nv_bfloat16*)Cm)[(size_t)r1 * ldc + col] = pr;
                } else {
                    *(float2*)&((float*)Cm)[(size_t)r1 * ldc + col] = make_float2(v2, v3);
                }
            }
        }
    }
}

// plain GEMM wrapper (QKV, proj)
template<int ACT, bool RESID, int OUTBF>
__global__ __launch_bounds__(256) void tgemm_k(
    const __nv_bfloat16* __restrict__ A, int lda,
    const __nv_bfloat16* __restrict__ Bt,
    const float* __restrict__ bias,
    const float* __restrict__ resid,
    void* __restrict__ Cm, int ldc,
    int M, int Kk)
{
    int m0 = blockIdx.y * 128;
    if (m0 >= M) return;
    gemm_body<false, ACT, RESID, OUTBF>(A, lda, Bt, bias, resid, Cm, ldc,
                                        M, Kk, nullptr, m0, blockIdx.x * 128);
}

// ---------------- batched expert GEMMs (blockIdx.z = expert) ----------------
template<int MODE>
__global__ __launch_bounds__(256) void egemm_k(
    const __nv_bfloat16* __restrict__ hA,
    const __nv_bfloat16* __restrict__ mid1,
    const __nv_bfloat16* __restrict__ mid2,
    const __nv_bfloat16* __restrict__ Wt,
    const float* __restrict__ dBias, const float* __restrict__ sBias,
    void* __restrict__ Cout,
    const int* __restrict__ tok, const int* __restrict__ cnt)
{
    int z = blockIdx.z;
    int M = cnt[z];
    int m0 = blockIdx.y * 128;
    if (m0 >= M) return;
    int n0 = blockIdx.x * 128;
    bool deep = (MODE == 1) ? true : (z < 2);

    if (MODE == 0) {
        const __nv_bfloat16* W = deep ? Wt + WT_DW1 + (size_t)z * F_ * C_
                                      : Wt + WT_SW1 + (size_t)(z - 2) * F_ * C_;
        const float* bs = deep ? dBias + (size_t)z * F_ : sBias + (size_t)(z - 2) * F_;
        __nv_bfloat16* Cm = (__nv_bfloat16*)Cout + (size_t)z * N_ * F_;
        gemm_body<true, 1, false, 1>(hA, C_, W, bs, nullptr, Cm, F_,
                                     M, C_, tok + (size_t)z * N_, m0, n0);
    } else if (MODE == 1) {
        const __nv_bfloat16* A = mid1 + (size_t)z * N_ * F_;
        const __nv_bfloat16* W = Wt + WT_DW2 + (size_t)z * F_ * F_;
        const float* bs = dBias + (size_t)z * F_;
        __nv_bfloat16* Cm = (__nv_bfloat16*)Cout + (size_t)z * N_ * F_;
        gemm_body<false, 1, false, 1>(A, F_, W, bs, nullptr, Cm, F_,
                                      M, F_, nullptr, m0, n0);
    } else {
        const __nv_bfloat16* A = deep ? mid2 + (size_t)z * N_ * F_ : mid1 + (size_t)z * N_ * F_;
        const __nv_bfloat16* W = deep ? Wt + WT_DW3 + (size_t)z * C_ * F_
                                      : Wt + WT_SW2 + (size_t)(z - 2) * C_ * F_;
        const float* bs = deep ? dBias + (size_t)z * C_ : sBias + (size_t)(z - 2) * C_;
        float* Cm = (float*)Cout + (size_t)z * N_ * C_;
        gemm_body<false, 0, false, 0>(A, F_, W, bs, nullptr, Cm, C_,
                                      M, F_, nullptr, m0, n0);
    }
}

// ---------------- attention scores (bf16 mma; Q,K k-major/n-major natural) ----------------
__global__ __launch_bounds__(256) void attn_scores_tc(const __nv_bfloat16* __restrict__ qkv,
                                                      float* __restrict__ S) {
    int t0 = blockIdx.y * 128, s0 = blockIdx.x * 128;
    if (s0 > t0) return;
    int bh = blockIdx.z;
    int b = bh / H_, h = bh - b * H_;

    extern __shared__ char smraw[];
    __nv_bfloat16* Qs = (__nv_bfloat16*)smraw;   // [128][72]
    __nv_bfloat16* Ks = Qs + 128*72;             // [128 s][72 d]
    int tid = threadIdx.x;

    const __nv_bfloat16* qbase = qkv + (size_t)(b * T_ + t0) * C3_ + h * HS_;
    const __nv_bfloat16* kbase = qkv + (size_t)(b * T_ + s0) * C3_ + C_ + h * HS_;
    #pragma unroll
    for (int l = 0; l < 4; l++) {
        int idx = tid + l * 256;          // 0..1023
        int r = idx >> 3, q = idx & 7;    // row, 8-bf16 chunk
        cpa16(&Qs[r*72 + q*8], qbase + (size_t)r * C3_ + q * 8);
        cpa16(&Ks[r*72 + q*8], kbase + (size_t)r * C3_ + q * 8);
    }
    asm volatile("cp.async.commit_group;");
    asm volatile("cp.async.wait_group 0;");
    __syncthreads();

    int wid = tid >> 5, lane = tid & 31;
    int warpM = (wid >> 2) * 64, warpN = (wid & 3) * 32;
    int g = lane >> 2, tg = lane & 3;
    int rowIn = ((lane >> 3) & 1) * 8 + (lane & 7);
    int colIn = (lane >> 4) * 8;

    float acc[4][4][4];
    #pragma unroll
    for (int i = 0; i < 4; i++)
        #pragma unroll
        for (int j = 0; j < 4; j++)
            #pragma unroll
            for (int r = 0; r < 4; r++) acc[i][j][r] = 0.f;

    #pragma unroll
    for (int ks = 0; ks < 4; ks++) {     // k16 steps over d=64
        unsigned af[4][4];
        #pragma unroll
        for (int i = 0; i < 4; i++)
            ldsm4(af[i][0], af[i][1], af[i][2], af[i][3],
                  &Qs[(warpM + i*16 + rowIn)*72 + ks*16 + colIn]);
        unsigned bq[2][4];
        #pragma unroll
        for (int j2 = 0; j2 < 2; j2++)
            ldsm4(bq[j2][0], bq[j2][1], bq[j2][2], bq[j2][3],
                  &Ks[(warpN + j2*16 + rowIn)*72 + ks*16 + colIn]);
        #pragma unroll
        for (int i = 0; i < 4; i++) {
            mma_bf16(acc[i][0], af[i], bq[0][0], bq[0][2]);
            mma_bf16(acc[i][1], af[i], bq[0][1], bq[0][3]);
            mma_bf16(acc[i][2], af[i], bq[1][0], bq[1][2]);
            mma_bf16(acc[i][3], af[i], bq[1][1], bq[1][3]);
        }
    }

    const float scale = 0.03608439182435161f;   // 768^-0.5
    float* op = S + ((size_t)bh * T_ + t0) * T_ + s0;
    #pragma unroll
    for (int i = 0; i < 4; i++) {
        int r0 = warpM + i * 16 + g;
        int r1 = r0 + 8;
        #pragma unroll
        for (int j = 0; j < 4; j++) {
            int col = warpN + j * 8 + tg * 2;
            *(float2*)&op[(size_t)r0 * T_ + col] =
                make_float2(acc[i][j][0] * scale, acc[i][j][1] * scale);
            *(float2*)&op[(size_t)r1 * T_ + col] =
                make_float2(acc[i][j][2] * scale, acc[i][j][3] * scale);
        }
    }
}

// ---------------- causal softmax: S fp32 -> P bf16, zero-fill to tile edge ----------------
__global__ __launch_bounds__(128) void softmax_causal_kernel(const float* __restrict__ S,
                                                             __nv_bfloat16* __restrict__ P) {
    int row = blockIdx.x;
    int t = row & (T_ - 1);
    const float* p = S + (size_t)row * T_;
    __nv_bfloat16* q = P + (size_t)row * T_;
    int len = t + 1;
    int end = ((t >> 7) + 1) << 7;
    int tid = threadIdx.x;
    __shared__ float sh[4];

    float mx = -1e30f;
    for (int s = tid; s < len; s += 128) mx = fmaxf(mx, p[s]);
    #pragma unroll
    for (int o = 16; o; o >>= 1) mx = fmaxf(mx, __shfl_down_sync(0xffffffffu, mx, o));
    if ((tid & 31) == 0) sh[tid >> 5] = mx;
    __syncthreads();
    mx = fmaxf(fmaxf(sh[0], sh[1]), fmaxf(sh[2], sh[3]));
    __syncthreads();

    float sum = 0.f;
    __shared__ float ex[1024];
    for (int s = tid; s < len; s += 128) { float e = __expf(p[s] - mx); ex[s] = e; sum += e; }
    #pragma unroll
    for (int o = 16; o; o >>= 1) sum += __shfl_down_sync(0xffffffffu, sum, o);
    if ((tid & 31) == 0) sh[tid >> 5] = sum;
    __syncthreads();
    sum = sh[0] + sh[1] + sh[2] + sh[3];
    float inv = 1.f / sum;
    for (int s = tid; s < len; s += 128) q[s] = __float2bfloat16_rn(ex[s] * inv);
    for (int s = len + tid; s < end; s += 128) q[s] = __float2bfloat16_rn(0.f);
}

// ---------------- PV (bf16 mma; V via ldsm.trans; 4-stage ring) ----------------
__global__ __launch_bounds__(256) void attn_pv_tc(const __nv_bfloat16* __restrict__ qkv,
                                                  const __nv_bfloat16* __restrict__ P,
                                                  __nv_bfloat16* __restrict__ O) {
    int t0 = blockIdx.x * 128;
    int bh = blockIdx.y;
    int b = bh / H_, h = bh - b * H_;

    extern __shared__ char smraw[];
    __nv_bfloat16* sA = (__nv_bfloat16*)smraw;   // [4][128][STB_]  P tile
    __nv_bfloat16* sV = sA + 4*128*STB_;         // [4][32][72]     V tile [s][d]

    int tid = threadIdx.x;
    const __nv_bfloat16* aPtr = P + ((size_t)bh * T_ + t0) * T_;
    const __nv_bfloat16* vbase = qkv + (size_t)(b * T_) * C3_ + 2 * C_ + h * HS_;

    int ldRow = tid & 127;
    int ldCol = (tid >> 7) * 16;
    int vS = tid >> 3;          // 0..31
    int vC = (tid & 7) * 8;     // d chunk

    int nTiles = (t0 + 128) / 32;   // 4..32

    #pragma unroll
    for (int s = 0; s < 3; s++) {
        int k0 = s * 32;
        __nv_bfloat16* dA = sA + (s*128 + ldRow)*STB_ + ldCol;
        cpa16(dA,     aPtr + (size_t)ldRow * T_ + k0 + ldCol);
        cpa16(dA + 8, aPtr + (size_t)ldRow * T_ + k0 + ldCol + 8);
        cpa16(&sV[(s*32 + vS)*72 + vC], vbase + (size_t)(k0 + vS) * C3_ + vC);
        asm volatile("cp.async.commit_group;");
    }

    int wid = tid >> 5, lane = tid & 31;
    int warpM = (wid >> 1) * 32;    // 4 warps in M
    int warpN = (wid & 1) * 32;     // 2 warps in d
    int g = lane >> 2, tg = lane & 3;
    int rowIn = ((lane >> 3) & 1) * 8 + (lane & 7);
    int colIn = (lane >> 4) * 8;

    float acc[2][4][4];
    #pragma unroll
    for (int i = 0; i < 2; i++)
        #pragma unroll
        for (int j = 0; j < 4; j++)
            #pragma unroll
            for (int r = 0; r < 4; r++) acc[i][j][r] = 0.f;

    for (int t = 0; t < nTiles; t++) {
        asm volatile("cp.async.wait_group 2;");
        __syncthreads();

        int tn = t + 3;
        if (tn < nTiles) {
            int stg = tn & 3;
            int k0 = tn * 32;
            __nv_bfloat16* dA = sA + (stg*128 + ldRow)*STB_ + ldCol;
            cpa16(dA,     aPtr + (size_t)ldRow * T_ + k0 + ldCol);
            cpa16(dA + 8, aPtr + (size_t)ldRow * T_ + k0 + ldCol + 8);
            cpa16(&sV[(stg*32 + vS)*72 + vC], vbase + (size_t)(k0 + vS) * C3_ + vC);
        }
        asm volatile("cp.async.commit_group;");

        int buf = t & 3;
        const __nv_bfloat16* Ab = sA + buf*128*STB_;
        const __nv_bfloat16* Vb = sV + buf*32*72;
        #pragma unroll
        for (int s = 0; s < 2; s++) {
            unsigned af[2][4];
            #pragma unroll
            for (int i = 0; i < 2; i++)
                ldsm4(af[i][0], af[i][1], af[i][2], af[i][3],
                      &Ab[(warpM + i*16 + rowIn)*STB_ + s*16 + colIn]);
            // V trans: matrices over [s rows][d chunks]; after trans:
            // d0-7 k-tile: (r0,r1)  d8-15: (r2,r3)
            unsigned bv[2][4];
            #pragma unroll
            for (int j2 = 0; j2 < 2; j2++)
                ldsm4t(bv[j2][0], bv[j2][1], bv[j2][2], bv[j2][3],
                       &Vb[(s*16 + rowIn)*72 + warpN + j2*16 + colIn]);
            #pragma unroll
            for (int i = 0; i < 2; i++) {
                mma_bf16(acc[i][0], af[i], bv[0][0], bv[0][1]);
                mma_bf16(acc[i][1], af[i], bv[0][2], bv[0][3]);
                mma_bf16(acc[i][2], af[i], bv[1][0], bv[1][1]);
                mma_bf16(acc[i][3], af[i], bv[1][2], bv[1][3]);
            }
        }
    }

    #pragma unroll
    for (int i = 0; i < 2; i++) {
        int r0 = warpM + i * 16 + g;
        int r1 = r0 + 8;
        #pragma unroll
        for (int j = 0; j < 4; j++) {
            int col = h * HS_ + warpN + j * 8 + tg * 2;
            __nv_bfloat162 p0, p1;
            p0.x = __float2bfloat16_rn(acc[i][j][0]); p0.y = __float2bfloat16_rn(acc[i][j][1]);
            p1.x = __float2bfloat16_rn(acc[i][j][2]); p1.y = __float2bfloat16_rn(acc[i][j][3]);
            *(__nv_bfloat162*)&O[(size_t)(b * T_ + t0 + r0) * C_ + col] = p0;
            *(__nv_bfloat162*)&O[(size_t)(b * T_ + t0 + r1) * C_ + col] = p1;
        }
    }
}

// ---------------- router: noisy top-2 + assignment + slot table ----------------
__global__ __launch_bounds__(256) void router_kernel(
    const float* __restrict__ h2,
    const float* __restrict__ wr, const float* __restrict__ br,
    const float* __restrict__ wn, const float* __restrict__ bn,
    const float* __restrict__ noise, const float* __restrict__ temp_p,
    int* __restrict__ cnt, int* __restrict__ tok, float* __restrict__ gw,
    int* __restrict__ slot)
{
    int n = blockIdx.x * 8 + (threadIdx.x >> 5);
    if (n >= N_) return;
    int lane = threadIdx.x & 31;
    float ar[E_] = {}, an[E_] = {};
    const float* hp = h2 + (size_t)n * C_;
    for (int c = lane; c < C_; c += 32) {
        float hv = hp[c];
        const float* wrp = wr + c * E_;
        const float* wnp = wn + c * E_;
        #pragma unroll
        for (int e = 0; e < E_; e++) {
            ar[e] = fmaf(hv, wrp[e], ar[e]);
            an[e] = fmaf(hv, wnp[e], an[e]);
        }
    }
    #pragma unroll
    for (int e = 0; e < E_; e++) {
        #pragma unroll
        for (int o = 16; o; o >>= 1) {
            ar[e] += __shfl_down_sync(0xffffffffu, ar[e], o);
            an[e] += __shfl_down_sync(0xffffffffu, an[e], o);
        }
    }
    if (lane == 0) {
        float t = fminf(fmaxf(*temp_p, 0.5f), 2.0f);
        float noisy[E_];
        #pragma unroll
        for (int e = 0; e < E_; e++) {
            float logit = ar[e] + br[e];
            float z = an[e] + bn[e];
            float sp = fmaxf(z, 0.f) + log1pf(expf(-fabsf(z)));
            noisy[e] = logit + t * noise[(size_t)n * E_ + e] * sp;
        }
        int i1 = 0;
        #pragma unroll
        for (int e = 1; e < E_; e++) if (noisy[e] > noisy[i1]) i1 = e;
        int i2 = -1;
        #pragma unroll
        for (int e = 0; e < E_; e++)
            if (e != i1 && (i2 < 0 || noisy[e] > noisy[i2])) i2 = e;
        float m = fmaxf(noisy[i1], noisy[i2]);
        float e1 = __expf(noisy[i1] - m), e2 = __expf(noisy[i2] - m);
        float inv = 1.f / (e1 + e2);
        int p1 = atomicAdd(&cnt[i1], 1); tok[i1 * N_ + p1] = n; gw[i1 * N_ + p1] = e1 * inv;
        int p2 = atomicAdd(&cnt[i2], 1); tok[i2 * N_ + p2] = n; gw[i2 * N_ + p2] = e2 * inv;
        slot[2 * n]     = i1 * N_ + p1;
        slot[2 * n + 1] = i2 * N_ + p2;
    }
}

// ---------------- slot epilogue: Yc[s] = gate * LN(h2[n] + Yc[s]) ----------------
__global__ __launch_bounds__(256) void expert_epi_slots(
    float* __restrict__ Yc, const float* __restrict__ h2,
    const int* __restrict__ tok, const float* __restrict__ gw,
    const int* __restrict__ slot,
    const float* __restrict__ dlg, const float* __restrict__ dlb,
    const float* __restrict__ slg, const float* __restrict__ slb)
{
    int s = slot[blockIdx.x];
    int z = s >> 13;            // /N_
    bool deep = z < 2;
    const float* lg = deep ? dlg + (size_t)z * C_ : slg + (size_t)(z - 2) * C_;
    const float* lb = deep ? dlb + (size_t)z * C_ : slb + (size_t)(z - 2) * C_;
    int n = tok[s];
    float g = gw[s];
    float* yp = Yc + (size_t)s * C_;
    const float* hp = h2 + (size_t)n * C_;
    int t = threadIdx.x;
    float z0 = hp[t]       + yp[t];
    float z1 = hp[t + 256] + yp[t + 256];
    float z2 = hp[t + 512] + yp[t + 512];
    float mean = blockReduceSum256(z0 + z1 + z2) * (1.0f / C_);
    float d0 = z0 - mean, d1 = z1 - mean, d2 = z2 - mean;
    float var = blockReduceSum256(d0*d0 + d1*d1 + d2*d2) * (1.0f / C_);
    float rstd = rsqrtf(var + 1e-5f);
    yp[t]       = g * (d0 * rstd * lg[t]       + lb[t]);
    yp[t + 256] = g * (d1 * rstd * lg[t + 256] + lb[t + 256]);
    yp[t + 512] = g * (d2 * rstd * lg[t + 512] + lb[t + 512]);
}

// ---------------- final combine: out[n] += Yc[slot0] + Yc[slot1] ----------------
__global__ __launch_bounds__(256) void combine_kernel(
    const float* __restrict__ Yc, const int* __restrict__ slot,
    float* __restrict__ out)
{
    int n = blockIdx.x;
    const float* a = Yc + (size_t)slot[2 * n] * C_;
    const float* b = Yc + (size_t)slot[2 * n + 1] * C_;
    float* op = out + (size_t)n * C_;
    int t = threadIdx.x;
    op[t]       += a[t]       + b[t];
    op[t + 256] += a[t + 256] + b[t + 256];
    op[t + 512] += a[t + 512] + b[t + 512];
}

// ---------------- launch ----------------
extern "C" void kernel_launch(void* const* d_in, const int* in_sizes, int n_in,
                              void* d_out, int out_size) {
    const float* x         = (const float*)d_in[0];
    const float* rnoise    = (const float*)d_in[1];
    const float* wq        = (const float*)d_in[2];
    const float* wk        = (const float*)d_in[3];
    const float* wv        = (const float*)d_in[4];
    const float* w_proj    = (const float*)d_in[5];
    const float* b_proj    = (const float*)d_in[6];
    const float* ln1_g     = (const float*)d_in[7];
    const float* ln1_b     = (const float*)d_in[8];
    const float* ln2_g     = (const float*)d_in[9];
    const float* ln2_b     = (const float*)d_in[10];
    const float* w_route   = (const float*)d_in[11];
    const float* b_route   = (const float*)d_in[12];
    const float* w_noise   = (const float*)d_in[13];
    const float* b_noise   = (const float*)d_in[14];
    const float* temp      = (const float*)d_in[15];
    const float* deep_w1   = (const float*)d_in[16];
    const float* deep_b1   = (const float*)d_in[17];
    const float* deep_w2   = (const float*)d_in[18];
    const float* deep_b2   = (const float*)d_in[19];
    const float* deep_w3   = (const float*)d_in[20];
    const float* deep_b3   = (const float*)d_in[21];
    const float* deep_ln_g = (const float*)d_in[22];
    const float* deep_ln_b = (const float*)d_in[23];
    const float* simple_w1   = (const float*)d_in[24];
    const float* simple_b1   = (const float*)d_in[25];
    const float* simple_w2   = (const float*)d_in[26];
    const float* simple_b2   = (const float*)d_in[27];
    const float* simple_ln_g = (const float*)d_in[28];
    const float* simple_ln_b = (const float*)d_in[29];

    float* out = (float*)d_out;

    __nv_bfloat16 *h1, *qkv, *P, *o, *mid1, *mid2, *Wqkv, *Wt;
    float *S, *h2, *Yc, *gw;
    int *cnt, *tok, *slot;
    cudaGetSymbolAddress((void**)&h1,   g_h1);
    cudaGetSymbolAddress((void**)&qkv,  g_qkv);
    cudaGetSymbolAddress((void**)&S,    g_S);
    cudaGetSymbolAddress((void**)&P,    g_P);
    cudaGetSymbolAddress((void**)&o,    g_o);
    cudaGetSymbolAddress((void**)&h2,   g_h2);
    cudaGetSymbolAddress((void**)&mid1, g_mid1);
    cudaGetSymbolAddress((void**)&mid2, g_mid2);
    cudaGetSymbolAddress((void**)&Yc,   g_Yc);
    cudaGetSymbolAddress((void**)&Wqkv, g_Wqkv);
    cudaGetSymbolAddress((void**)&Wt,   g_Wt);
    cudaGetSymbolAddress((void**)&cnt,  g_cnt);
    cudaGetSymbolAddress((void**)&tok,  g_tok);
    cudaGetSymbolAddress((void**)&gw,   g_gw);
    cudaGetSymbolAddress((void**)&slot, g_slot);

    // raise dynamic smem limits (idempotent)
    cudaFuncSetAttribute((const void*)tgemm_k<0,false,1>, cudaFuncAttributeMaxDynamicSharedMemorySize, TG_SMEM);
    cudaFuncSetAttribute((const void*)tgemm_k<0,true,0>,  cudaFuncAttributeMaxDynamicSharedMemorySize, TG_SMEM);
    cudaFuncSetAttribute((const void*)egemm_k<0>, cudaFuncAttributeMaxDynamicSharedMemorySize, TG_SMEM);
    cudaFuncSetAttribute((const void*)egemm_k<1>, cudaFuncAttributeMaxDynamicSharedMemorySize, TG_SMEM);
    cudaFuncSetAttribute((const void*)egemm_k<2>, cudaFuncAttributeMaxDynamicSharedMemorySize, TG_SMEM);
    cudaFuncSetAttribute((const void*)attn_scores_tc, cudaFuncAttributeMaxDynamicSharedMemorySize, SC_SMEM);
    cudaFuncSetAttribute((const void*)attn_pv_tc,     cudaFuncAttributeMaxDynamicSharedMemorySize, PV_SMEM);

    zero_cnt_kernel<<<1, 32>>>(cnt);
    pack_wqkv_kernel<<<(C_ * C3_ + 255) / 256, 256>>>(wq, wk, wv);

    // transpose weights to n-major bf16
    dim3 tb(32, 8);
    transpose_bf16_kernel<<<dim3(C_/32, C_/32, 1), tb>>>(w_proj,    Wt + WT_PROJ, C_, C_);
    transpose_bf16_kernel<<<dim3(F_/32, C_/32, 2), tb>>>(deep_w1,   Wt + WT_DW1,  C_, F_);
    transpose_bf16_kernel<<<dim3(F_/32, F_/32, 2), tb>>>(deep_w2,   Wt + WT_DW2,  F_, F_);
    transpose_bf16_kernel<<<dim3(C_/32, F_/32, 2), tb>>>(deep_w3,   Wt + WT_DW3,  F_, C_);
    transpose_bf16_kernel<<<dim3(F_/32, C_/32, 6), tb>>>(simple_w1, Wt + WT_SW1,  C_, F_);
    transpose_bf16_kernel<<<dim3(C_/32, F_/32, 6), tb>>>(simple_w2, Wt + WT_SW2,  F_, C_);

    // ln1 -> h1 bf16 ; qkv = h1 @ Wqkv^T (bf16 out)
    ln_kernel<<<N_, 256>>>(x, ln1_g, ln1_b, nullptr, h1);
    tgemm_k<0, false, 1><<<dim3(C3_ / 128, N_ / 128), 256, TG_SMEM>>>(
        h1, C_, Wqkv, nullptr, nullptr, qkv, C3_, N_, C_);

    // attention
    attn_scores_tc<<<dim3(T_ / 128, T_ / 128, BH_), 256, SC_SMEM>>>(qkv, S);
    softmax_causal_kernel<<<BH_ * T_, 128>>>(S, P);
    attn_pv_tc<<<dim3(T_ / 128, BH_), 256, PV_SMEM>>>(qkv, P, o);

    // out = x + o @ w_proj + b_proj (fp32 out)
    tgemm_k<0, true, 0><<<dim3(C_ / 128, N_ / 128), 256, TG_SMEM>>>(
        o, C_, Wt + WT_PROJ, b_proj, x, out, C_, N_, C_);

    // ln2 -> h2 fp32 + h2r bf16 (reuses h1) ; router
    ln_kernel<<<N_, 256>>>(out, ln2_g, ln2_b, h2, h1);
    router_kernel<<<N_ / 8, 256>>>(h2, w_route, b_route, w_noise, b_noise,
                                   rnoise, temp, cnt, tok, gw, slot);

    // experts, batched across blockIdx.z
    egemm_k<0><<<dim3(F_ / 128, N_ / 128, E_), 256, TG_SMEM>>>(
        h1, mid1, mid2, Wt, deep_b1, simple_b1, mid1, tok, cnt);
    egemm_k<1><<<dim3(F_ / 128, N_ / 128, 2), 256, TG_SMEM>>>(
        h1, mid1, mid2, Wt, deep_b2, nullptr, mid2, tok, cnt);
    egemm_k<2><<<dim3(C_ / 128, N_ / 128, E_), 256, TG_SMEM>>>(
        h1, mid1, mid2, Wt, deep_b3, simple_b2, Yc, tok, cnt);

    // slot epilogue + final combine
    expert_epi_slots<<<2 * N_, 256>>>(Yc, h2, tok, gw, slot,
                                      deep_ln_g, deep_ln_b,
                                      simple_ln_g, simple_ln_b);
    combine_kernel<<<N_, 256>>>(Yc, slot, out);
}